// round 15
// baseline (speedup 1.0000x reference)
#include <cuda_runtime.h>
#include <cstdint>

// SVDHead: batched Kabsch rotation — persistent, double-buffered TMA pipeline.
//   Grid = 148 (one CTA per SM), 2 x 56KB smem buffers. Each block loops over
//   ~28 batches: while computing batch i from buffer A, batch i+1's
//   cp.async.bulk (3 copies: src 24KB, tgt 24KB, mask 8KB) streams into buffer
//   B. Compute (~1700 cyc incl. SVD tail) < fetch (~2400 cyc at per-SM share
//   of the LTS cap) -> TMA-bound, memory pipe never idle.
//   Per batch: 256 threads reduce H = src^T diag(mask) tgt from smem; thread 0
//   runs branchless MUFU-fast one-sided Jacobi 3x3 SVD (3 sweeps), writes
//   R = V diag(1,1,sgn) U^T (sign on smallest singular pair, sgn=sign(det H)).
//
//   R14 lesson: single-shot TMA per block had no fetch/compute overlap (DRAM
//   67%). R11 lesson: persistent LDG blew registers; TMA keeps regs ~45.
//
// B=4096, N=2048.

#define BB 4096
#define NN 2048
#define THREADS 256
#define GRID 148

#define SRC_BYTES  (NN * 3 * 4)                  // 24576
#define MASK_BYTES (NN * 4)                      // 8192
#define TX_BYTES   (2 * SRC_BYTES + MASK_BYTES)  // 57344
#define BUF_BYTES  TX_BYTES

// dynamic smem layout
#define SM_MBAR  0                    // two 8-byte mbarriers
#define SM_BUF0  128
#define SM_BUF1  (SM_BUF0 + BUF_BYTES)
#define SM_TOTAL (SM_BUF1 + BUF_BYTES)   // 114816

__device__ __forceinline__ void issue_batch_tma(uint32_t mbar, uint32_t buf_smem,
                                                const float* src, const float* tgt,
                                                const float* mask_tgt, int b)
{
    asm volatile("mbarrier.arrive.expect_tx.shared.b64 _, [%0], %1;"
                 :: "r"(mbar), "r"((uint32_t)TX_BYTES) : "memory");
    const char* gsrc = (const char*)(src)      + (size_t)b * SRC_BYTES;
    const char* gtgt = (const char*)(tgt)      + (size_t)b * SRC_BYTES;
    const char* gmsk = (const char*)(mask_tgt) + (size_t)b * MASK_BYTES;
    asm volatile("cp.async.bulk.shared::cluster.global.mbarrier::complete_tx::bytes "
                 "[%0], [%1], %2, [%3];"
                 :: "r"(buf_smem), "l"(gsrc), "r"((uint32_t)SRC_BYTES), "r"(mbar) : "memory");
    asm volatile("cp.async.bulk.shared::cluster.global.mbarrier::complete_tx::bytes "
                 "[%0], [%1], %2, [%3];"
                 :: "r"(buf_smem + SRC_BYTES), "l"(gtgt), "r"((uint32_t)SRC_BYTES), "r"(mbar) : "memory");
    asm volatile("cp.async.bulk.shared::cluster.global.mbarrier::complete_tx::bytes "
                 "[%0], [%1], %2, [%3];"
                 :: "r"(buf_smem + 2 * SRC_BYTES), "l"(gmsk), "r"((uint32_t)MASK_BYTES), "r"(mbar) : "memory");
}

__global__ __launch_bounds__(THREADS)
void svdhead_pipe_kernel(const float* __restrict__ src,
                         const float* __restrict__ tgt,
                         const float* __restrict__ mask_tgt,
                         float* __restrict__ out)
{
    extern __shared__ char smem[];
    const int tid  = threadIdx.x;
    const int lane = tid & 31;
    const int warp = tid >> 5;

    const uint32_t smem_base = (uint32_t)__cvta_generic_to_shared(smem);

    __shared__ float red[THREADS / 32][9];

    if (tid == 0) {
        asm volatile("mbarrier.init.shared.b64 [%0], 1;" :: "r"(smem_base + SM_MBAR) : "memory");
        asm volatile("mbarrier.init.shared.b64 [%0], 1;" :: "r"(smem_base + SM_MBAR + 8) : "memory");
        asm volatile("fence.proxy.async.shared::cta;" ::: "memory");
        // prologue: prefetch iterations 0 and 1
        issue_batch_tma(smem_base + SM_MBAR,     smem_base + SM_BUF0,
                        src, tgt, mask_tgt, blockIdx.x);
        const int b1 = blockIdx.x + GRID;
        if (b1 < BB)
            issue_batch_tma(smem_base + SM_MBAR + 8, smem_base + SM_BUF1,
                            src, tgt, mask_tgt, b1);
    }
    __syncthreads();

    int it = 0;
    for (int b = blockIdx.x; b < BB; b += GRID, ++it) {
        const int      bufi = it & 1;
        const uint32_t mbar = smem_base + SM_MBAR + 8 * bufi;
        const uint32_t bufo = bufi ? SM_BUF1 : SM_BUF0;
        const uint32_t par  = (it >> 1) & 1;   // k-th use of this buffer -> parity k&1

        // wait for this buffer's TMA
        {
            uint32_t done;
            asm volatile(
                "{\n\t.reg .pred p;\n\t"
                "mbarrier.try_wait.parity.shared.b64 p, [%1], %2;\n\t"
                "selp.b32 %0, 1, 0, p;\n\t}"
                : "=r"(done) : "r"(mbar), "r"(par) : "memory");
            while (!done) {
                asm volatile(
                    "{\n\t.reg .pred p;\n\t"
                    "mbarrier.try_wait.parity.shared.b64 p, [%1], %2, 0x989680;\n\t"
                    "selp.b32 %0, 1, 0, p;\n\t}"
                    : "=r"(done) : "r"(mbar), "r"(par) : "memory");
            }
        }

        // ---- masked outer-product reduction from smem ---------------------
        const float4* s4 = reinterpret_cast<const float4*>(smem + bufo);
        const float4* t4 = reinterpret_cast<const float4*>(smem + bufo + SRC_BYTES);
        const float4* m4 = reinterpret_cast<const float4*>(smem + bufo + 2 * SRC_BYTES);

        float h[9];
        #pragma unroll
        for (int i = 0; i < 9; ++i) h[i] = 0.f;

        #define ACC_POINT(sx, sy, sz, tx, ty, tz, mm)                                              \
            {                                                                                      \
                float w0 = (mm) * (tx), w1 = (mm) * (ty), w2 = (mm) * (tz);                        \
                h[0] = fmaf((sx), w0, h[0]); h[1] = fmaf((sx), w1, h[1]); h[2] = fmaf((sx), w2, h[2]); \
                h[3] = fmaf((sy), w0, h[3]); h[4] = fmaf((sy), w1, h[4]); h[5] = fmaf((sy), w2, h[5]); \
                h[6] = fmaf((sz), w0, h[6]); h[7] = fmaf((sz), w1, h[7]); h[8] = fmaf((sz), w2, h[8]); \
            }

        #pragma unroll
        for (int half = 0; half < 2; ++half) {
            const int g = tid + half * THREADS;   // group of 4 points
            float4 sa = s4[g * 3 + 0];
            float4 sb = s4[g * 3 + 1];
            float4 sc = s4[g * 3 + 2];
            float4 ta = t4[g * 3 + 0];
            float4 tb = t4[g * 3 + 1];
            float4 tc = t4[g * 3 + 2];
            float4 m  = m4[g];

            ACC_POINT(sa.x, sa.y, sa.z, ta.x, ta.y, ta.z, m.x)
            ACC_POINT(sa.w, sb.x, sb.y, ta.w, tb.x, tb.y, m.y)
            ACC_POINT(sb.z, sb.w, sc.x, tb.z, tb.w, tc.x, m.z)
            ACC_POINT(sc.y, sc.z, sc.w, tc.y, tc.z, tc.w, m.w)
        }
        #undef ACC_POINT

        // warp reduce
        #pragma unroll
        for (int i = 0; i < 9; ++i) {
            #pragma unroll
            for (int off = 16; off > 0; off >>= 1)
                h[i] += __shfl_down_sync(0xffffffffu, h[i], off);
        }

        if (lane == 0) {
            #pragma unroll
            for (int i = 0; i < 9; ++i) red[warp][i] = h[i];
        }
        __syncthreads();   // all reads of buf done; red[] populated

        // refill this buffer for iteration it+2 (thread 255: not in warp 0,
        // so TMA issue overlaps warp 0's SVD below)
        if (tid == THREADS - 1) {
            const int bn = b + 2 * GRID;
            if (bn < BB)
                issue_batch_tma(mbar, smem_base + bufo, src, tgt, mask_tgt, bn);
        }

        if (warp == 0) {
            float hv = 0.f;
            if (lane < 9) {
                #pragma unroll
                for (int w = 0; w < THREADS / 32; ++w) hv += red[w][lane];
            }
            // gather the 9 sums into lane 0
            float e0 = __shfl_sync(0xffffffffu, hv, 0);
            float e1 = __shfl_sync(0xffffffffu, hv, 1);
            float e2 = __shfl_sync(0xffffffffu, hv, 2);
            float e3 = __shfl_sync(0xffffffffu, hv, 3);
            float e4 = __shfl_sync(0xffffffffu, hv, 4);
            float e5 = __shfl_sync(0xffffffffu, hv, 5);
            float e6 = __shfl_sync(0xffffffffu, hv, 6);
            float e7 = __shfl_sync(0xffffffffu, hv, 7);
            float e8 = __shfl_sync(0xffffffffu, hv, 8);

            if (lane == 0) {
                float A[3][3], V[3][3];
                A[0][0] = e0; A[0][1] = e1; A[0][2] = e2;
                A[1][0] = e3; A[1][1] = e4; A[1][2] = e5;
                A[2][0] = e6; A[2][1] = e7; A[2][2] = e8;
                #pragma unroll
                for (int r = 0; r < 3; ++r)
                    #pragma unroll
                    for (int c = 0; c < 3; ++c)
                        V[r][c] = (r == c) ? 1.f : 0.f;

                const float det =
                      A[0][0] * (A[1][1] * A[2][2] - A[1][2] * A[2][1])
                    - A[0][1] * (A[1][0] * A[2][2] - A[1][2] * A[2][0])
                    + A[0][2] * (A[1][0] * A[2][1] - A[1][1] * A[2][0]);

                // one-sided Jacobi, 3 sweeps, branchless, MUFU-fast.
                #pragma unroll
                for (int sweep = 0; sweep < 3; ++sweep) {
                    #pragma unroll
                    for (int pq = 0; pq < 3; ++pq) {
                        const int p = (pq == 2) ? 1 : 0;
                        const int q = (pq == 0) ? 1 : 2;
                        float ap0 = A[0][p], ap1 = A[1][p], ap2 = A[2][p];
                        float aq0 = A[0][q], aq1 = A[1][q], aq2 = A[2][q];
                        float alpha = ap0 * ap0 + ap1 * ap1 + ap2 * ap2;
                        float beta  = aq0 * aq0 + aq1 * aq1 + aq2 * aq2;
                        float gamma = ap0 * aq0 + ap1 * aq1 + ap2 * aq2;
                        float gden  = copysignf(fmaxf(fabsf(gamma), 1e-30f), gamma);
                        float zeta  = __fdividef(beta - alpha, 2.f * gden);  // MUFU.RCP
                        float w     = fmaf(zeta, zeta, 1.f);
                        float sqw   = w * rsqrtf(w);                         // MUFU.RSQ
                        float t     = __fdividef(copysignf(1.f, zeta), fabsf(zeta) + sqw);
                        float c     = rsqrtf(fmaf(t, t, 1.f));               // MUFU.RSQ
                        float s     = c * t;
                        #pragma unroll
                        for (int r = 0; r < 3; ++r) {
                            float xp = A[r][p], xq = A[r][q];
                            A[r][p] = c * xp - s * xq;
                            A[r][q] = s * xp + c * xq;
                            float vp = V[r][p], vq = V[r][q];
                            V[r][p] = c * vp - s * vq;
                            V[r][q] = s * vp + c * vq;
                        }
                    }
                }

                float U[3][3], sv[3];
                #pragma unroll
                for (int j = 0; j < 3; ++j) {
                    float d = A[0][j] * A[0][j] + A[1][j] * A[1][j] + A[2][j] * A[2][j];
                    sv[j] = d;
                    float inv = rsqrtf(fmaxf(d, 1e-30f));
                    U[0][j] = A[0][j] * inv;
                    U[1][j] = A[1][j] * inv;
                    U[2][j] = A[2][j] * inv;
                }
                int jmin = 0;
                if (sv[1] < sv[jmin]) jmin = 1;
                if (sv[2] < sv[jmin]) jmin = 2;

                const float sgn = (det < 0.f) ? -1.f : 1.f;
                float coef[3] = {1.f, 1.f, 1.f};
                coef[jmin] = sgn;

                float* o = out + (size_t)b * 9;
                #pragma unroll
                for (int i = 0; i < 3; ++i)
                    #pragma unroll
                    for (int k = 0; k < 3; ++k) {
                        float acc = coef[0] * V[i][0] * U[k][0]
                                  + coef[1] * V[i][1] * U[k][1]
                                  + coef[2] * V[i][2] * U[k][2];
                        __stcs(&o[i * 3 + k], acc);
                    }
            }
        }
        __syncthreads();   // red[] reuse safety for next iteration
    }
}

extern "C" void kernel_launch(void* const* d_in, const int* in_sizes, int n_in,
                              void* d_out, int out_size)
{
    const float* src      = (const float*)d_in[0];  // src_pts3d  [B,N,3]
    const float* tgt      = (const float*)d_in[1];  // tgt_pts3d  [B,N,3]
    // d_in[2] = kpt_src_mask — unused by the reference einsum
    const float* mask_tgt = (const float*)d_in[3];  // kpt_tgt_mask [B,N]
    float* out = (float*)d_out;

    cudaFuncSetAttribute(svdhead_pipe_kernel,
                         cudaFuncAttributeMaxDynamicSharedMemorySize, SM_TOTAL);
    svdhead_pipe_kernel<<<GRID, THREADS, SM_TOTAL>>>(src, tgt, mask_tgt, out);
}

// round 16
// speedup vs baseline: 1.0006x; 1.0006x over previous
#include <cuda_runtime.h>
#include <cstdint>

// SVDHead: batched Kabsch rotation — fused kernel, per-thread cp.async staging.
//   Grid = 4096 (one batch per block, the shape that works). Each thread issues
//   6 cp.async.cg (16B) for its two point-groups of src+tgt into smem — bytes
//   in flight cost ZERO destination registers (R12's LDG ceiling was the
//   64-reg file: 5.4KB/SM in flight vs ~9KB needed). Mask arrives via two
//   __ldcs register loads. Two commit groups let half1's fetch overlap half0's
//   compute. Each thread reads only smem it wrote -> no syncthreads in the
//   pipeline. smem 48KB/CTA -> 4 CTAs/SM (32 warps).
//   Reduce + branchless MUFU-fast 3x3 Jacobi SVD tail identical to R12:
//   R = V diag(1,1,sgn) U^T, sign on smallest singular pair, sgn = sign(det H).
//
// B=4096, N=2048.

#define BB 4096
#define NN 2048
#define THREADS 256

#define SRC_BYTES (NN * 3 * 4)             // 24576
#define SM_SRC 0
#define SM_TGT SRC_BYTES
#define SM_DYN (2 * SRC_BYTES)             // 49152

__device__ __forceinline__ void cp16(uint32_t dst_smem, const void* gsrc)
{
    asm volatile("cp.async.cg.shared.global [%0], [%1], 16;"
                 :: "r"(dst_smem), "l"(gsrc) : "memory");
}

__global__ __launch_bounds__(THREADS)
void svdhead_cpasync_kernel(const float* __restrict__ src,
                            const float* __restrict__ tgt,
                            const float* __restrict__ mask_tgt,
                            float* __restrict__ out)
{
    extern __shared__ char smem[];
    const int b    = blockIdx.x;
    const int tid  = threadIdx.x;
    const int lane = tid & 31;
    const int warp = tid >> 5;

    const uint32_t smem_base = (uint32_t)__cvta_generic_to_shared(smem);

    const float4* s4g = reinterpret_cast<const float4*>(src)      + (size_t)b * (NN * 3 / 4);
    const float4* t4g = reinterpret_cast<const float4*>(tgt)      + (size_t)b * (NN * 3 / 4);
    const float4* m4g = reinterpret_cast<const float4*>(mask_tgt) + (size_t)b * (NN / 4);

    const int g0 = tid;             // half 0 group
    const int g1 = tid + THREADS;   // half 1 group

    // ---- issue async copies: half0 group, then half1 group ---------------
    cp16(smem_base + SM_SRC + (uint32_t)g0 * 48 +  0, &s4g[g0 * 3 + 0]);
    cp16(smem_base + SM_SRC + (uint32_t)g0 * 48 + 16, &s4g[g0 * 3 + 1]);
    cp16(smem_base + SM_SRC + (uint32_t)g0 * 48 + 32, &s4g[g0 * 3 + 2]);
    cp16(smem_base + SM_TGT + (uint32_t)g0 * 48 +  0, &t4g[g0 * 3 + 0]);
    cp16(smem_base + SM_TGT + (uint32_t)g0 * 48 + 16, &t4g[g0 * 3 + 1]);
    cp16(smem_base + SM_TGT + (uint32_t)g0 * 48 + 32, &t4g[g0 * 3 + 2]);
    asm volatile("cp.async.commit_group;" ::: "memory");

    cp16(smem_base + SM_SRC + (uint32_t)g1 * 48 +  0, &s4g[g1 * 3 + 0]);
    cp16(smem_base + SM_SRC + (uint32_t)g1 * 48 + 16, &s4g[g1 * 3 + 1]);
    cp16(smem_base + SM_SRC + (uint32_t)g1 * 48 + 32, &s4g[g1 * 3 + 2]);
    cp16(smem_base + SM_TGT + (uint32_t)g1 * 48 +  0, &t4g[g1 * 3 + 0]);
    cp16(smem_base + SM_TGT + (uint32_t)g1 * 48 + 16, &t4g[g1 * 3 + 1]);
    cp16(smem_base + SM_TGT + (uint32_t)g1 * 48 + 32, &t4g[g1 * 3 + 2]);
    asm volatile("cp.async.commit_group;" ::: "memory");

    // masks via register loads (only 8 data regs) — overlap with cp.async
    float4 m0 = __ldcs(&m4g[g0]);
    float4 m1 = __ldcs(&m4g[g1]);

    float h[9];
    #pragma unroll
    for (int i = 0; i < 9; ++i) h[i] = 0.f;

    const float4* s4 = reinterpret_cast<const float4*>(smem + SM_SRC);
    const float4* t4 = reinterpret_cast<const float4*>(smem + SM_TGT);

    #define ACC_POINT(sx, sy, sz, tx, ty, tz, mm)                                              \
        {                                                                                      \
            float w0 = (mm) * (tx), w1 = (mm) * (ty), w2 = (mm) * (tz);                        \
            h[0] = fmaf((sx), w0, h[0]); h[1] = fmaf((sx), w1, h[1]); h[2] = fmaf((sx), w2, h[2]); \
            h[3] = fmaf((sy), w0, h[3]); h[4] = fmaf((sy), w1, h[4]); h[5] = fmaf((sy), w2, h[5]); \
            h[6] = fmaf((sz), w0, h[6]); h[7] = fmaf((sz), w1, h[7]); h[8] = fmaf((sz), w2, h[8]); \
        }

    // ---- half 0: wait for its group only (half1 still in flight) ---------
    asm volatile("cp.async.wait_group 1;" ::: "memory");
    {
        float4 sa = s4[g0 * 3 + 0];
        float4 sb = s4[g0 * 3 + 1];
        float4 sc = s4[g0 * 3 + 2];
        float4 ta = t4[g0 * 3 + 0];
        float4 tb = t4[g0 * 3 + 1];
        float4 tc = t4[g0 * 3 + 2];
        ACC_POINT(sa.x, sa.y, sa.z, ta.x, ta.y, ta.z, m0.x)
        ACC_POINT(sa.w, sb.x, sb.y, ta.w, tb.x, tb.y, m0.y)
        ACC_POINT(sb.z, sb.w, sc.x, tb.z, tb.w, tc.x, m0.z)
        ACC_POINT(sc.y, sc.z, sc.w, tc.y, tc.z, tc.w, m0.w)
    }

    // ---- half 1 ----------------------------------------------------------
    asm volatile("cp.async.wait_group 0;" ::: "memory");
    {
        float4 sa = s4[g1 * 3 + 0];
        float4 sb = s4[g1 * 3 + 1];
        float4 sc = s4[g1 * 3 + 2];
        float4 ta = t4[g1 * 3 + 0];
        float4 tb = t4[g1 * 3 + 1];
        float4 tc = t4[g1 * 3 + 2];
        ACC_POINT(sa.x, sa.y, sa.z, ta.x, ta.y, ta.z, m1.x)
        ACC_POINT(sa.w, sb.x, sb.y, ta.w, tb.x, tb.y, m1.y)
        ACC_POINT(sb.z, sb.w, sc.x, tb.z, tb.w, tc.x, m1.z)
        ACC_POINT(sc.y, sc.z, sc.w, tc.y, tc.z, tc.w, m1.w)
    }
    #undef ACC_POINT

    // ---- reduce ----------------------------------------------------------
    #pragma unroll
    for (int i = 0; i < 9; ++i) {
        #pragma unroll
        for (int off = 16; off > 0; off >>= 1)
            h[i] += __shfl_down_sync(0xffffffffu, h[i], off);
    }

    __shared__ float red[THREADS / 32][9];
    if (lane == 0) {
        #pragma unroll
        for (int i = 0; i < 9; ++i) red[warp][i] = h[i];
    }
    __syncthreads();

    if (warp == 0) {
        float hv = 0.f;
        if (lane < 9) {
            #pragma unroll
            for (int w = 0; w < THREADS / 32; ++w) hv += red[w][lane];
            red[0][lane] = hv;
        }
        __syncwarp();

        if (lane == 0) {
            float A[3][3], V[3][3];
            #pragma unroll
            for (int r = 0; r < 3; ++r)
                #pragma unroll
                for (int c = 0; c < 3; ++c) {
                    A[r][c] = red[0][r * 3 + c];
                    V[r][c] = (r == c) ? 1.f : 0.f;
                }

            const float det =
                  A[0][0] * (A[1][1] * A[2][2] - A[1][2] * A[2][1])
                - A[0][1] * (A[1][0] * A[2][2] - A[1][2] * A[2][0])
                + A[0][2] * (A[1][0] * A[2][1] - A[1][1] * A[2][0]);

            // one-sided Jacobi, 3 sweeps, fully unrolled, branchless, MUFU-fast.
            #pragma unroll
            for (int sweep = 0; sweep < 3; ++sweep) {
                #pragma unroll
                for (int pq = 0; pq < 3; ++pq) {
                    const int p = (pq == 2) ? 1 : 0;
                    const int q = (pq == 0) ? 1 : 2;
                    float ap0 = A[0][p], ap1 = A[1][p], ap2 = A[2][p];
                    float aq0 = A[0][q], aq1 = A[1][q], aq2 = A[2][q];
                    float alpha = ap0 * ap0 + ap1 * ap1 + ap2 * ap2;
                    float beta  = aq0 * aq0 + aq1 * aq1 + aq2 * aq2;
                    float gamma = ap0 * aq0 + ap1 * aq1 + ap2 * aq2;
                    float gden  = copysignf(fmaxf(fabsf(gamma), 1e-30f), gamma);
                    float zeta  = __fdividef(beta - alpha, 2.f * gden);  // MUFU.RCP
                    float w     = fmaf(zeta, zeta, 1.f);
                    float sqw   = w * rsqrtf(w);                         // MUFU.RSQ
                    float t     = __fdividef(copysignf(1.f, zeta), fabsf(zeta) + sqw);
                    float c     = rsqrtf(fmaf(t, t, 1.f));               // MUFU.RSQ
                    float s     = c * t;
                    #pragma unroll
                    for (int r = 0; r < 3; ++r) {
                        float xp = A[r][p], xq = A[r][q];
                        A[r][p] = c * xp - s * xq;
                        A[r][q] = s * xp + c * xq;
                        float vp = V[r][p], vq = V[r][q];
                        V[r][p] = c * vp - s * vq;
                        V[r][q] = s * vp + c * vq;
                    }
                }
            }

            // singular values = column norms; U columns = normalized A columns
            float U[3][3], sv[3];
            #pragma unroll
            for (int j = 0; j < 3; ++j) {
                float d = A[0][j] * A[0][j] + A[1][j] * A[1][j] + A[2][j] * A[2][j];
                sv[j] = d;
                float inv = rsqrtf(fmaxf(d, 1e-30f));
                U[0][j] = A[0][j] * inv;
                U[1][j] = A[1][j] * inv;
                U[2][j] = A[2][j] * inv;
            }
            int jmin = 0;
            if (sv[1] < sv[jmin]) jmin = 1;
            if (sv[2] < sv[jmin]) jmin = 2;

            const float sgn = (det < 0.f) ? -1.f : 1.f;
            float coef[3] = {1.f, 1.f, 1.f};
            coef[jmin] = sgn;

            // R = V diag(coef) U^T — streaming stores
            float* o = out + (size_t)b * 9;
            #pragma unroll
            for (int i = 0; i < 3; ++i)
                #pragma unroll
                for (int k = 0; k < 3; ++k) {
                    float acc = coef[0] * V[i][0] * U[k][0]
                              + coef[1] * V[i][1] * U[k][1]
                              + coef[2] * V[i][2] * U[k][2];
                    __stcs(&o[i * 3 + k], acc);
                }
        }
    }
}

extern "C" void kernel_launch(void* const* d_in, const int* in_sizes, int n_in,
                              void* d_out, int out_size)
{
    const float* src      = (const float*)d_in[0];  // src_pts3d  [B,N,3]
    const float* tgt      = (const float*)d_in[1];  // tgt_pts3d  [B,N,3]
    // d_in[2] = kpt_src_mask — unused by the reference einsum
    const float* mask_tgt = (const float*)d_in[3];  // kpt_tgt_mask [B,N]
    float* out = (float*)d_out;

    cudaFuncSetAttribute(svdhead_cpasync_kernel,
                         cudaFuncAttributeMaxDynamicSharedMemorySize, SM_DYN);
    svdhead_cpasync_kernel<<<BB, THREADS, SM_DYN>>>(src, tgt, mask_tgt, out);
}

// round 17
// speedup vs baseline: 1.4717x; 1.4709x over previous
#include <cuda_runtime.h>

// SVDHead: batched Kabsch rotation — FINAL kernel (R12 config, best measured).
//   Single fused kernel, grid=4096 (one batch per block), 256 threads.
//   Per block: 14 front-batched float4 __ldcs streaming loads per thread
//   (24 warps x 14 x 32 lanes x 16B ~ 172KB/SM in flight), 9-accumulator
//   masked outer-product H = src^T diag(mask) tgt, warp/smem tree reduce,
//   then thread 0 runs a branchless MUFU-fast one-sided Jacobi 3x3 SVD
//   (3 sweeps) and writes R = V diag(1,1,sgn) U^T (sign on the smallest
//   singular pair, sgn = sign(det H)) via __stcs.
//
//   Measured: 37.8us kernel @ 6302 GB/s = 98.4% of the ~6.3TB/s full-chip
//   LTS plateau (traffic is exactly minimal: 238MB). Perturbations tried and
//   rejected: 4 CTAs/SM (R10, regs squeezed), persistent LDG (R11, regs
//   ballooned), PDL (R6), bulk-TMA single-shot (R14), TMA pipeline (R15),
//   per-thread cp.async (R16) — all regressed. This is the wall.
//
// B=4096, N=2048.

#define BB 4096
#define NN 2048
#define THREADS 256

__global__ __launch_bounds__(THREADS, 3)
void svdhead_fused_kernel(const float* __restrict__ src,
                          const float* __restrict__ tgt,
                          const float* __restrict__ mask_tgt,
                          float* __restrict__ out)
{
    const int b    = blockIdx.x;
    const int tid  = threadIdx.x;
    const int lane = tid & 31;
    const int warp = tid >> 5;

    float h[9];
    #pragma unroll
    for (int i = 0; i < 9; ++i) h[i] = 0.f;

    const float4* s4 = reinterpret_cast<const float4*>(src)      + (size_t)b * (NN * 3 / 4);
    const float4* t4 = reinterpret_cast<const float4*>(tgt)      + (size_t)b * (NN * 3 / 4);
    const float4* m4 = reinterpret_cast<const float4*>(mask_tgt) + (size_t)b * (NN / 4);

    // Front-batch ALL loads for both halves (14 float4 streaming loads in flight)
    const int g0 = tid;             // half 0
    const int g1 = tid + THREADS;   // half 1

    float4 sa0 = __ldcs(&s4[g0 * 3 + 0]);
    float4 sb0 = __ldcs(&s4[g0 * 3 + 1]);
    float4 sc0 = __ldcs(&s4[g0 * 3 + 2]);
    float4 ta0 = __ldcs(&t4[g0 * 3 + 0]);
    float4 tb0 = __ldcs(&t4[g0 * 3 + 1]);
    float4 tc0 = __ldcs(&t4[g0 * 3 + 2]);
    float4 m0  = __ldcs(&m4[g0]);
    float4 sa1 = __ldcs(&s4[g1 * 3 + 0]);
    float4 sb1 = __ldcs(&s4[g1 * 3 + 1]);
    float4 sc1 = __ldcs(&s4[g1 * 3 + 2]);
    float4 ta1 = __ldcs(&t4[g1 * 3 + 0]);
    float4 tb1 = __ldcs(&t4[g1 * 3 + 1]);
    float4 tc1 = __ldcs(&t4[g1 * 3 + 2]);
    float4 m1  = __ldcs(&m4[g1]);

    #define ACC_POINT(sx, sy, sz, tx, ty, tz, mm)                                              \
        {                                                                                      \
            float w0 = (mm) * (tx), w1 = (mm) * (ty), w2 = (mm) * (tz);                        \
            h[0] = fmaf((sx), w0, h[0]); h[1] = fmaf((sx), w1, h[1]); h[2] = fmaf((sx), w2, h[2]); \
            h[3] = fmaf((sy), w0, h[3]); h[4] = fmaf((sy), w1, h[4]); h[5] = fmaf((sy), w2, h[5]); \
            h[6] = fmaf((sz), w0, h[6]); h[7] = fmaf((sz), w1, h[7]); h[8] = fmaf((sz), w2, h[8]); \
        }

    ACC_POINT(sa0.x, sa0.y, sa0.z, ta0.x, ta0.y, ta0.z, m0.x)
    ACC_POINT(sa0.w, sb0.x, sb0.y, ta0.w, tb0.x, tb0.y, m0.y)
    ACC_POINT(sb0.z, sb0.w, sc0.x, tb0.z, tb0.w, tc0.x, m0.z)
    ACC_POINT(sc0.y, sc0.z, sc0.w, tc0.y, tc0.z, tc0.w, m0.w)

    ACC_POINT(sa1.x, sa1.y, sa1.z, ta1.x, ta1.y, ta1.z, m1.x)
    ACC_POINT(sa1.w, sb1.x, sb1.y, ta1.w, tb1.x, tb1.y, m1.y)
    ACC_POINT(sb1.z, sb1.w, sc1.x, tb1.z, tb1.w, tc1.x, m1.z)
    ACC_POINT(sc1.y, sc1.z, sc1.w, tc1.y, tc1.z, tc1.w, m1.w)

    #undef ACC_POINT

    // warp reduce
    #pragma unroll
    for (int i = 0; i < 9; ++i) {
        #pragma unroll
        for (int off = 16; off > 0; off >>= 1)
            h[i] += __shfl_down_sync(0xffffffffu, h[i], off);
    }

    __shared__ float red[THREADS / 32][9];
    if (lane == 0) {
        #pragma unroll
        for (int i = 0; i < 9; ++i) red[warp][i] = h[i];
    }
    __syncthreads();

    // cross-warp reduce inside warp 0 (threads 0..8 own one H element each),
    // then thread 0 runs the SVD. Other warps exit; their memory work is done.
    if (warp == 0) {
        float hv = 0.f;
        if (lane < 9) {
            #pragma unroll
            for (int w = 0; w < THREADS / 32; ++w) hv += red[w][lane];
            red[0][lane] = hv;
        }
        __syncwarp();

        if (lane == 0) {
            float A[3][3], V[3][3];
            #pragma unroll
            for (int r = 0; r < 3; ++r)
                #pragma unroll
                for (int c = 0; c < 3; ++c) {
                    A[r][c] = red[0][r * 3 + c];
                    V[r][c] = (r == c) ? 1.f : 0.f;
                }

            const float det =
                  A[0][0] * (A[1][1] * A[2][2] - A[1][2] * A[2][1])
                - A[0][1] * (A[1][0] * A[2][2] - A[1][2] * A[2][0])
                + A[0][2] * (A[1][0] * A[2][1] - A[1][1] * A[2][0]);

            // one-sided Jacobi, 3 sweeps, fully unrolled, branchless, MUFU-fast.
            #pragma unroll
            for (int sweep = 0; sweep < 3; ++sweep) {
                #pragma unroll
                for (int pq = 0; pq < 3; ++pq) {
                    const int p = (pq == 2) ? 1 : 0;
                    const int q = (pq == 0) ? 1 : 2;
                    float ap0 = A[0][p], ap1 = A[1][p], ap2 = A[2][p];
                    float aq0 = A[0][q], aq1 = A[1][q], aq2 = A[2][q];
                    float alpha = ap0 * ap0 + ap1 * ap1 + ap2 * ap2;
                    float beta  = aq0 * aq0 + aq1 * aq1 + aq2 * aq2;
                    float gamma = ap0 * aq0 + ap1 * aq1 + ap2 * aq2;
                    float gden  = copysignf(fmaxf(fabsf(gamma), 1e-30f), gamma);
                    float zeta  = __fdividef(beta - alpha, 2.f * gden);  // MUFU.RCP
                    float w     = fmaf(zeta, zeta, 1.f);
                    float sqw   = w * rsqrtf(w);                         // MUFU.RSQ
                    float t     = __fdividef(copysignf(1.f, zeta), fabsf(zeta) + sqw);
                    float c     = rsqrtf(fmaf(t, t, 1.f));               // MUFU.RSQ
                    float s     = c * t;
                    #pragma unroll
                    for (int r = 0; r < 3; ++r) {
                        float xp = A[r][p], xq = A[r][q];
                        A[r][p] = c * xp - s * xq;
                        A[r][q] = s * xp + c * xq;
                        float vp = V[r][p], vq = V[r][q];
                        V[r][p] = c * vp - s * vq;
                        V[r][q] = s * vp + c * vq;
                    }
                }
            }

            // singular values = column norms; U columns = normalized A columns
            float U[3][3], sv[3];
            #pragma unroll
            for (int j = 0; j < 3; ++j) {
                float d = A[0][j] * A[0][j] + A[1][j] * A[1][j] + A[2][j] * A[2][j];
                sv[j] = d;
                float inv = rsqrtf(fmaxf(d, 1e-30f));
                U[0][j] = A[0][j] * inv;
                U[1][j] = A[1][j] * inv;
                U[2][j] = A[2][j] * inv;
            }
            int jmin = 0;
            if (sv[1] < sv[jmin]) jmin = 1;
            if (sv[2] < sv[jmin]) jmin = 2;

            const float sgn = (det < 0.f) ? -1.f : 1.f;
            float coef[3] = {1.f, 1.f, 1.f};
            coef[jmin] = sgn;

            // R = V diag(coef) U^T — streaming stores
            float* o = out + (size_t)b * 9;
            #pragma unroll
            for (int i = 0; i < 3; ++i)
                #pragma unroll
                for (int k = 0; k < 3; ++k) {
                    float acc = coef[0] * V[i][0] * U[k][0]
                              + coef[1] * V[i][1] * U[k][1]
                              + coef[2] * V[i][2] * U[k][2];
                    __stcs(&o[i * 3 + k], acc);
                }
        }
    }
}

extern "C" void kernel_launch(void* const* d_in, const int* in_sizes, int n_in,
                              void* d_out, int out_size)
{
    const float* src      = (const float*)d_in[0];  // src_pts3d  [B,N,3]
    const float* tgt      = (const float*)d_in[1];  // tgt_pts3d  [B,N,3]
    // d_in[2] = kpt_src_mask — unused by the reference einsum
    const float* mask_tgt = (const float*)d_in[3];  // kpt_tgt_mask [B,N]
    float* out = (float*)d_out;

    svdhead_fused_kernel<<<BB, THREADS>>>(src, tgt, mask_tgt, out);
}